// round 2
// baseline (speedup 1.0000x reference)
#include <cuda_runtime.h>
#include <math_constants.h>

// Problem sizes (fixed by the reference)
#define NN 262144
#define EE (NN * 32)

// Packed per-node data: 2 x float4 per node (32B), L2-resident (8 MB)
//   nodeA = { actualArea, c2 = aA^2/(area*rho), fA = area*rho, p }
//   nodeB = { vx, vy, ax, ay }
__device__ float4 g_node[NN * 2];
// Accumulators: 2 x float4 per node (8 MB), hit with red.global.add.v4.f32
//   accA = { kSum1x, kSum1y, accelx, accely }
//   accB = { kSum2, source, kernelSum, pad }
__device__ float4 g_acc[NN * 2];

__global__ void prep_kernel(const float* __restrict__ area,
                            const float* __restrict__ actualArea,
                            const float* __restrict__ rho,
                            const float* __restrict__ density,
                            const float* __restrict__ pressure2,
                            const float2* __restrict__ vel,
                            const float2* __restrict__ acc)
{
    int n = blockIdx.x * blockDim.x + threadIdx.x;
    if (n >= NN) return;
    float aA = actualArea[n];
    float ar = area[n];
    float r  = rho[n];
    float fA = ar * r;
    float c2 = (aA * aA) / fA;
    float dr = density[n] * r;
    float p  = pressure2[n] / (dr * dr);
    float2 v = vel[n];
    float2 a = acc[n];
    g_node[2 * n + 0] = make_float4(aA, c2, fA, p);
    g_node[2 * n + 1] = make_float4(v.x, v.y, a.x, a.y);
    g_acc[2 * n + 0] = make_float4(0.f, 0.f, 0.f, 0.f);
    g_acc[2 * n + 1] = make_float4(0.f, 0.f, 0.f, 0.f);
}

__device__ __forceinline__ void red_add_v4(float4* addr, float a, float b, float c, float d) {
    asm volatile("red.global.add.v4.f32 [%0], {%1, %2, %3, %4};"
                 :: "l"(addr), "f"(a), "f"(b), "f"(c), "f"(d) : "memory");
}

__global__ void edge_kernel(const int* __restrict__ nbr,       // [2, E]
                            const float* __restrict__ radial,  // [E]
                            const float2* __restrict__ dirs,   // [E, 2]
                            const float* __restrict__ support_p,
                            const float* __restrict__ dt_p)
{
    int e = blockIdx.x * blockDim.x + threadIdx.x;
    if (e >= EE) return;

    float h  = __ldg(support_p);
    float dt = __ldg(dt_p);
    const float C_W = 7.0f / CUDART_PI_F;
    float K = (C_W / (h * h * h)) * 20.0f;

    int i = __ldg(&nbr[e]);
    int j = __ldg(&nbr[EE + e]);

    float q = radial[e];
    float2 d = dirs[e];
    float om = 1.0f - q;
    float mag = K * q * om * om * om;
    float gx = -d.x * mag;
    float gy = -d.y * mag;
    float grad2 = gx * gx + gy * gy;

    float4 ja = g_node[2 * j + 0];  // {aA, c2, fA, p}
    float4 jb = g_node[2 * j + 1];  // {vx, vy, ax, ay}
    float4 ia = g_node[2 * i + 0];
    float4 ib = g_node[2 * i + 1];

    // kSum1
    float kx = ja.x * gx;
    float ky = ja.x * gy;
    // kSum2
    float k2 = ja.y * grad2;
    // pressure accel: facA = -(area*rho)[j]
    float pc = -ja.z * (ia.w + ja.w);
    float ax = pc * gx;
    float ay = pc * gy;
    // source: -dt * aA[j] * dot(vi - vj, g)
    float src = -dt * ja.x * ((ib.x - jb.x) * gx + (ib.y - jb.y) * gy);
    // kernelSum: dt^2 * aA[j] * dot(ai - aj, g)
    float ks = dt * dt * ja.x * ((ib.z - jb.z) * gx + (ib.w - jb.w) * gy);

    red_add_v4(&g_acc[2 * i + 0], kx, ky, ax, ay);
    red_add_v4(&g_acc[2 * i + 1], k2, src, ks, 0.0f);
}

__global__ void final_kernel(float* __restrict__ out, const float* __restrict__ dt_p)
{
    int n = blockIdx.x * blockDim.x + threadIdx.x;
    if (n >= NN) return;
    float dt = __ldg(dt_p);
    float4 A = g_acc[2 * n + 0];   // {kSum1x, kSum1y, accelx, accely}
    float4 B = g_acc[2 * n + 1];   // {kSum2, source, kernelSum, pad}
    float4 na = g_node[2 * n + 0]; // {aA, c2, fA, p}
    float fac = -dt * dt * na.x;
    float mass = na.z;             // area * rho
    float alpha = (fac / mass) * (A.x * A.x + A.y * A.y) + fac * B.x;
    out[5 * n + 0] = alpha;
    out[5 * n + 1] = A.z;
    out[5 * n + 2] = A.w;
    out[5 * n + 3] = B.y;
    out[5 * n + 4] = B.z;
}

extern "C" void kernel_launch(void* const* d_in, const int* in_sizes, int n_in,
                              void* d_out, int out_size)
{
    const float*  fluidArea         = (const float*)d_in[0];
    const float*  fluidActualArea   = (const float*)d_in[1];
    const float*  fluidRestDensity  = (const float*)d_in[2];
    const float*  fluidDensity      = (const float*)d_in[3];
    const float*  fluidPressure2    = (const float*)d_in[4];
    const float2* fluidPredVel      = (const float2*)d_in[5];
    const float2* fluidPredAccel    = (const float2*)d_in[6];
    const float*  fluidRadial       = (const float*)d_in[7];
    const float2* fluidDistances    = (const float2*)d_in[8];
    const int*    fluidNeighbors    = (const int*)d_in[9];
    const float*  support           = (const float*)d_in[10];
    const float*  dt                = (const float*)d_in[11];
    float* out = (float*)d_out;

    prep_kernel<<<(NN + 255) / 256, 256>>>(fluidArea, fluidActualArea,
                                           fluidRestDensity, fluidDensity,
                                           fluidPressure2, fluidPredVel,
                                           fluidPredAccel);
    edge_kernel<<<(EE + 255) / 256, 256>>>(fluidNeighbors, fluidRadial,
                                           fluidDistances, support, dt);
    final_kernel<<<(NN + 255) / 256, 256>>>(out, dt);
}